// round 3
// baseline (speedup 1.0000x reference)
#include <cuda_runtime.h>
#include <cstdint>
#include <cstddef>

#define KC   512      // number of centers
#define DDIM 128      // feature dim
#define NMAX 200192   // padded max points

// ---------------- scratch (device globals: no allocation allowed) ----------
__device__ float g_c2[KC];
__device__ float g_sums[KC * DDIM];
__device__ int   g_counts[KC];
__device__ int   g_assign[NMAX];

// ---------------- packed f32x2 helpers (Blackwell FFMA2) -------------------
__device__ __forceinline__ unsigned long long pk2(float lo, float hi) {
    unsigned long long r;
    asm("mov.b64 %0, {%1, %2};" : "=l"(r) : "f"(lo), "f"(hi));
    return r;
}
__device__ __forceinline__ unsigned long long ffma2(unsigned long long a,
                                                    unsigned long long b,
                                                    unsigned long long c) {
    unsigned long long d;
    asm("fma.rn.f32x2 %0, %1, %2, %3;" : "=l"(d) : "l"(a), "l"(b), "l"(c));
    return d;
}
__device__ __forceinline__ void upk2(unsigned long long v, float& lo, float& hi) {
    asm("mov.b64 {%0, %1}, %2;" : "=f"(lo), "=f"(hi) : "l"(v));
}

// ---------------- prep: zero sums/counts, compute ||c_k||^2 ----------------
__global__ void prep_kernel(const float* __restrict__ C) {
    int k = blockIdx.x;      // 0..511
    int t = threadIdx.x;     // 0..127
    g_sums[k * DDIM + t] = 0.0f;
    if (t == 0) g_counts[k] = 0;
    float v = C[k * DDIM + t];
    v *= v;
    #pragma unroll
    for (int off = 16; off >= 1; off >>= 1)
        v += __shfl_down_sync(0xffffffffu, v, off);
    __shared__ float red[4];
    if ((t & 31) == 0) red[t >> 5] = v;
    __syncthreads();
    if (t == 0) g_c2[k] = (red[0] + red[1]) + (red[2] + red[3]);
}

// ---------------- fused distance-GEMM + argmin -----------------------------
// CTA: 128 points x all 512 centers (4 tiles of 128). 256 threads, 8x8 micro.
// smem: Fs[d][p] 128x128 + Cs[d][c] 128x128 = 128 KB, 1 CTA/SM.
__global__ void __launch_bounds__(256, 1)
assign_kernel(const float* __restrict__ F, const float* __restrict__ C,
              int N, float* __restrict__ out_assign) {
    extern __shared__ float sm[];
    float* Fs = sm;                 // [d*128 + p]
    float* Cs = sm + DDIM * 128;    // [d*128 + c]

    const int tid = threadIdx.x;
    const int tx = tid & 15;        // center sub-tile (8 centers)
    const int ty = tid >> 4;        // point  sub-tile (8 points)
    const int p_local = tid & 127;  // loader lane -> point/center row
    const int c0 = tid >> 7;        // loader chunk phase (0..1)
    const long base_pt = (long)blockIdx.x * 128;

    // Load F tile transposed into smem (clamped for tail CTA).
    {
        long gp = base_pt + p_local;
        if (gp > (long)N - 1) gp = (long)N - 1;
        const float4* src = (const float4*)(F + (size_t)gp * DDIM);
        #pragma unroll
        for (int j = 0; j < 16; j++) {
            int c = c0 + j * 2;           // float4 chunk 0..31
            float4 v = src[c];
            int d0 = c * 4;
            Fs[(d0 + 0) * 128 + p_local] = v.x;
            Fs[(d0 + 1) * 128 + p_local] = v.y;
            Fs[(d0 + 2) * 128 + p_local] = v.z;
            Fs[(d0 + 3) * 128 + p_local] = v.w;
        }
    }

    float bestv[8];
    int   bestj[8];
    #pragma unroll
    for (int i = 0; i < 8; i++) { bestv[i] = 3.402823466e38f; bestj[i] = 0x7fffffff; }

    for (int ct = 0; ct < KC / 128; ct++) {
        __syncthreads();   // previous tile fully consumed (and Fs load done on ct=0)
        {
            int gr = ct * 128 + p_local;
            const float4* src = (const float4*)(C + (size_t)gr * DDIM);
            #pragma unroll
            for (int j = 0; j < 16; j++) {
                int c = c0 + j * 2;
                float4 v = src[c];
                int d0 = c * 4;
                Cs[(d0 + 0) * 128 + p_local] = v.x;
                Cs[(d0 + 1) * 128 + p_local] = v.y;
                Cs[(d0 + 2) * 128 + p_local] = v.z;
                Cs[(d0 + 3) * 128 + p_local] = v.w;
            }
        }
        __syncthreads();

        unsigned long long acc[8][4];
        #pragma unroll
        for (int i = 0; i < 8; i++)
            #pragma unroll
            for (int j = 0; j < 4; j++) acc[i][j] = 0ULL;

        #pragma unroll 4
        for (int d = 0; d < DDIM; d++) {
            const float4* fa = (const float4*)(Fs + d * 128 + ty * 8);
            float4 a0 = fa[0];
            float4 a1 = fa[1];
            const float4* cb = (const float4*)(Cs + d * 128 + tx * 8);
            float4 b0 = cb[0];
            float4 b1 = cb[1];
            unsigned long long bp0 = pk2(b0.x, b0.y);
            unsigned long long bp1 = pk2(b0.z, b0.w);
            unsigned long long bp2 = pk2(b1.x, b1.y);
            unsigned long long bp3 = pk2(b1.z, b1.w);
            float av[8] = {a0.x, a0.y, a0.z, a0.w, a1.x, a1.y, a1.z, a1.w};
            #pragma unroll
            for (int i = 0; i < 8; i++) {
                unsigned long long ad = pk2(av[i], av[i]);
                acc[i][0] = ffma2(ad, bp0, acc[i][0]);
                acc[i][1] = ffma2(ad, bp1, acc[i][1]);
                acc[i][2] = ffma2(ad, bp2, acc[i][2]);
                acc[i][3] = ffma2(ad, bp3, acc[i][3]);
            }
        }

        // epilogue: score = c2[j] - 2*dot ; argmin (first index on ties)
        const int jb = ct * 128 + tx * 8;
        #pragma unroll
        for (int i = 0; i < 8; i++) {
            #pragma unroll
            for (int jj = 0; jj < 4; jj++) {
                float s0, s1;
                upk2(acc[i][jj], s0, s1);
                int j0 = jb + jj * 2;
                float sc0 = fmaf(-2.0f, s0, g_c2[j0]);
                float sc1 = fmaf(-2.0f, s1, g_c2[j0 + 1]);
                if (sc0 < bestv[i] || (sc0 == bestv[i] && j0 < bestj[i])) { bestv[i] = sc0; bestj[i] = j0; }
                if (sc1 < bestv[i] || (sc1 == bestv[i] && (j0 + 1) < bestj[i])) { bestv[i] = sc1; bestj[i] = j0 + 1; }
            }
        }
    }

    // reduce across the 16 tx-threads of each point row (half-warp shuffles)
    #pragma unroll
    for (int i = 0; i < 8; i++) {
        float v = bestv[i];
        int   j = bestj[i];
        #pragma unroll
        for (int off = 8; off >= 1; off >>= 1) {
            float vo = __shfl_down_sync(0xffffffffu, v, off, 16);
            int   jo = __shfl_down_sync(0xffffffffu, j, off, 16);
            if (vo < v || (vo == v && jo < j)) { v = vo; j = jo; }
        }
        if (tx == 0) {
            long p = base_pt + ty * 8 + i;
            if (p < N) {
                g_assign[p] = j;
                out_assign[p] = (float)j;
            }
        }
    }
}

// ---------------- scatter: segment sums via REDG ---------------------------
// One warp per point: lane covers 4 dims (float4 load + 4 red.f32.add).
__global__ void scatter_kernel(const float* __restrict__ F, int N) {
    int w = (blockIdx.x * blockDim.x + threadIdx.x) >> 5;
    int lane = threadIdx.x & 31;
    if (w >= N) return;
    int a = g_assign[w];
    float4 v = ((const float4*)(F + (size_t)w * DDIM))[lane];
    float* base = g_sums + a * DDIM + lane * 4;
    atomicAdd(base + 0, v.x);
    atomicAdd(base + 1, v.y);
    atomicAdd(base + 2, v.z);
    atomicAdd(base + 3, v.w);
    if (lane == 0) atomicAdd(&g_counts[a], 1);
}

// ---------------- finalize: centers = sums / max(counts,1) -----------------
__global__ void finalize_kernel(float* __restrict__ out_centers) {
    int i = blockIdx.x * blockDim.x + threadIdx.x;
    if (i < KC * DDIM) {
        int k = i >> 7;
        float cnt = fmaxf((float)g_counts[k], 1.0f);
        out_centers[i] = g_sums[i] / cnt;
    }
}

// ---------------- launch ---------------------------------------------------
extern "C" void kernel_launch(void* const* d_in, const int* in_sizes, int n_in,
                              void* d_out, int out_size) {
    const float* F = (const float*)d_in[0];
    const float* C = (const float*)d_in[1];
    const int N = in_sizes[0] / DDIM;

    float* out = (float*)d_out;
    float* out_centers = out;                // [512*128]
    float* out_assign  = out + KC * DDIM;    // [N]

    prep_kernel<<<KC, DDIM>>>(C);

    const int smem_bytes = 2 * DDIM * 128 * (int)sizeof(float);  // 128 KB
    cudaFuncSetAttribute(assign_kernel,
                         cudaFuncAttributeMaxDynamicSharedMemorySize, smem_bytes);
    int grid = (N + 127) / 128;
    assign_kernel<<<grid, 256, smem_bytes>>>(F, C, N, out_assign);

    scatter_kernel<<<(N + 7) / 8, 256>>>(F, N);

    finalize_kernel<<<(KC * DDIM + 255) / 256, 256>>>(out_centers);
}

// round 5
// speedup vs baseline: 1.2878x; 1.2878x over previous
#include <cuda_runtime.h>
#include <cuda_bf16.h>
#include <cstdint>
#include <cstddef>

#define KC   512
#define DDIM 128
#define NMAX 200192

// ---------------- device scratch (no allocation allowed) -------------------
__device__ float    g_c2[KC];
__device__ float    g_sums[KC * DDIM];
__device__ int      g_counts[KC];
__device__ int      g_assign[NMAX];
// B fragments: [split(3)][ctile(4)][kstep(8)][ntile(16)][lane(32)][reg(2)]
__device__ uint32_t g_bfrag[3 * 4 * 8 * 16 * 32 * 2];   // 98304 u32 = 384 KB

// ---------------- helpers ---------------------------------------------------
__device__ __forceinline__ void split3f(float x, float& s0, float& s1, float& s2) {
    s0 = __bfloat162float(__float2bfloat16(x));
    float r = x - s0;
    s1 = __bfloat162float(__float2bfloat16(r));
    r -= s1;
    s2 = __bfloat162float(__float2bfloat16(r));
}
__device__ __forceinline__ uint32_t pack_bf(float lo, float hi) {
    __nv_bfloat16 l = __float2bfloat16(lo), h = __float2bfloat16(hi);
    uint16_t lb, hb;
    memcpy(&lb, &l, 2); memcpy(&hb, &h, 2);
    return (uint32_t)lb | ((uint32_t)hb << 16);
}
__device__ __forceinline__ void mma16816(float* d, const uint32_t* a, const uint32_t* b) {
    asm volatile(
        "mma.sync.aligned.m16n8k16.row.col.f32.bf16.bf16.f32 "
        "{%0,%1,%2,%3}, {%4,%5,%6,%7}, {%8,%9}, {%0,%1,%2,%3};"
        : "+f"(d[0]), "+f"(d[1]), "+f"(d[2]), "+f"(d[3])
        : "r"(a[0]), "r"(a[1]), "r"(a[2]), "r"(a[3]), "r"(b[0]), "r"(b[1]));
}
__device__ __forceinline__ void upd(float& bv, int& bj, float v, int j) {
    if (v < bv || (v == bv && j < bj)) { bv = v; bj = j; }
}

// ---------------- prep: zero sums/counts, ||c||^2 --------------------------
__global__ void prep_kernel(const float* __restrict__ C) {
    int k = blockIdx.x, t = threadIdx.x;
    g_sums[k * DDIM + t] = 0.0f;
    if (t == 0) g_counts[k] = 0;
    float v = C[k * DDIM + t];
    v *= v;
    #pragma unroll
    for (int off = 16; off >= 1; off >>= 1) v += __shfl_down_sync(0xffffffffu, v, off);
    __shared__ float red[4];
    if ((t & 31) == 0) red[t >> 5] = v;
    __syncthreads();
    if (t == 0) g_c2[k] = (red[0] + red[1]) + (red[2] + red[3]);
}

// ---------------- prep: convert centers into B fragments -------------------
// mma.m16n8k16 B frag (col-major k x n): lane(g=l>>2,tg=l&3):
//   b0 = {B[k0+2tg][n0+g], B[k0+2tg+1][n0+g]}, b1 = same at k+8. low half = even k.
__global__ void bfrag_kernel(const float* __restrict__ C) {
    int idx = blockIdx.x * 256 + threadIdx.x;      // < 98304
    int r    = idx & 1;
    int lane = (idx >> 1) & 31;
    int nt   = (idx >> 6) & 15;
    int ks   = (idx >> 10) & 7;
    int ct   = (idx >> 13) & 3;
    int s    = idx >> 15;
    int g = lane >> 2, tg = lane & 3;
    int c = ct * 128 + nt * 8 + g;
    int k = ks * 16 + 2 * tg + r * 8;
    float x0 = C[c * DDIM + k], x1 = C[c * DDIM + k + 1];
    float a0, a1, a2, b0, b1, b2;
    split3f(x0, a0, a1, a2);
    split3f(x1, b0, b1, b2);
    float lo = (s == 0) ? a0 : ((s == 1) ? a1 : a2);
    float hi = (s == 0) ? b0 : ((s == 1) ? b1 : b2);
    g_bfrag[idx] = pack_bf(lo, hi);
}

// ---------------- fused bf16x3 HMMA GEMM + argmin --------------------------
// CTA: 128 points x 512 centers. 8 warps, warp tile 64x32 per 128-center tile.
// smem: A fragments [split(3)][blk(64)=mtile*8+ks][lane(32)] x uint4 = 96 KB.
__global__ void __launch_bounds__(256, 1)
assign_kernel(const float* __restrict__ F, int N, float* __restrict__ out_assign) {
    extern __shared__ char smem[];
    uint32_t* As  = (uint32_t*)smem;               // 98304 B
    float*    c2s = (float*)(smem + 98304);        // 2 KB
    float*    redv = (float*)(smem + 100352);      // 2 KB
    int*      redj = (int*)(smem + 102400);        // 2 KB

    const int tid = threadIdx.x;
    const int lane = tid & 31, wid = tid >> 5;
    const int wm = wid >> 2, wn = wid & 3;
    const int g = lane >> 2, tg = lane & 3;
    const long base = (long)blockIdx.x * 128;

    c2s[tid]       = g_c2[tid];
    c2s[tid + 256] = g_c2[tid + 256];

    // ---- convert A (F tile) into fragment-ordered smem, 3 splits ----
    // A frag (row-major m x k): a0={F[g][2tg],F[g][2tg+1]}, a1=rows+8,
    //   a2=cols+8, a3=rows+8 cols+8 (within 16x16 tile). low half = even k.
    #pragma unroll
    for (int i = 0; i < 8; ++i) {
        int blk = (tid >> 5) + i * 8;              // 0..63: mtile*8 + ks
        int mt = blk >> 3, ks = blk & 7;
        long rA = base + mt * 16 + g;
        long rB = rA + 8;
        if (rA > (long)N - 1) rA = (long)N - 1;
        if (rB > (long)N - 1) rB = (long)N - 1;
        int kc = ks * 16 + 2 * tg;
        const float* F0 = F + (size_t)rA * DDIM;
        const float* F1 = F + (size_t)rB * DDIM;
        float2 p00 = *(const float2*)(F0 + kc);
        float2 p10 = *(const float2*)(F1 + kc);
        float2 p01 = *(const float2*)(F0 + kc + 8);
        float2 p11 = *(const float2*)(F1 + kc + 8);

        float x0[3], y0[3], x1[3], y1[3], x2[3], y2[3], x3[3], y3[3];
        split3f(p00.x, x0[0], x0[1], x0[2]); split3f(p00.y, y0[0], y0[1], y0[2]);
        split3f(p10.x, x1[0], x1[1], x1[2]); split3f(p10.y, y1[0], y1[1], y1[2]);
        split3f(p01.x, x2[0], x2[1], x2[2]); split3f(p01.y, y2[0], y2[1], y2[2]);
        split3f(p11.x, x3[0], x3[1], x3[2]); split3f(p11.y, y3[0], y3[1], y3[2]);

        #pragma unroll
        for (int s = 0; s < 3; ++s) {
            uint4 v;
            v.x = pack_bf(x0[s], y0[s]);   // a0
            v.y = pack_bf(x1[s], y1[s]);   // a1
            v.z = pack_bf(x2[s], y2[s]);   // a2
            v.w = pack_bf(x3[s], y3[s]);   // a3
            *(uint4*)(As + ((size_t)(s * 64 + blk) * 32 + lane) * 4) = v;
        }
    }
    __syncthreads();

    float bestv[4][2];
    int   bestj[4][2];
    #pragma unroll
    for (int mt = 0; mt < 4; ++mt)
        #pragma unroll
        for (int d = 0; d < 2; ++d) { bestv[mt][d] = 3.402823466e38f; bestj[mt][d] = 0x7fffffff; }

    const int CA[6] = {0, 0, 1, 1, 0, 2};
    const int CB[6] = {0, 1, 0, 1, 2, 0};

    for (int ct = 0; ct < 4; ++ct) {
        float acc[4][4][4];
        #pragma unroll
        for (int mt = 0; mt < 4; ++mt)
            #pragma unroll
            for (int nt = 0; nt < 4; ++nt)
                #pragma unroll
                for (int q = 0; q < 4; ++q) acc[mt][nt][q] = 0.0f;

        #pragma unroll 1
        for (int c = 0; c < 6; ++c) {
            const uint32_t* Abase = As + (size_t)CA[c] * 64 * 32 * 4;
            const uint32_t* Bbase = g_bfrag + (size_t)(CB[c] * 4 + ct) * 8 * 16 * 32 * 2;
            #pragma unroll
            for (int ks = 0; ks < 8; ++ks) {
                uint4 af[4];
                #pragma unroll
                for (int mt = 0; mt < 4; ++mt)
                    af[mt] = *(const uint4*)(Abase +
                        ((size_t)((wm * 4 + mt) * 8 + ks) * 32 + lane) * 4);
                uint2 bf[4];
                #pragma unroll
                for (int nt = 0; nt < 4; ++nt)
                    bf[nt] = *(const uint2*)(Bbase +
                        ((size_t)(ks * 16 + wn * 4 + nt) * 32 + lane) * 2);
                #pragma unroll
                for (int mt = 0; mt < 4; ++mt)
                    #pragma unroll
                    for (int nt = 0; nt < 4; ++nt)
                        mma16816(acc[mt][nt], (const uint32_t*)&af[mt], &bf[nt].x);
            }
        }

        // epilogue: score = c2 - 2*dot, fold into running argmin
        #pragma unroll
        for (int mt = 0; mt < 4; ++mt)
            #pragma unroll
            for (int nt = 0; nt < 4; ++nt) {
                int col = ct * 128 + wn * 32 + nt * 8 + 2 * tg;
                float c2a = c2s[col], c2b = c2s[col + 1];
                upd(bestv[mt][0], bestj[mt][0], fmaf(-2.0f, acc[mt][nt][0], c2a), col);
                upd(bestv[mt][0], bestj[mt][0], fmaf(-2.0f, acc[mt][nt][1], c2b), col + 1);
                upd(bestv[mt][1], bestj[mt][1], fmaf(-2.0f, acc[mt][nt][2], c2a), col);
                upd(bestv[mt][1], bestj[mt][1], fmaf(-2.0f, acc[mt][nt][3], c2b), col + 1);
            }
    }

    // ---- reduce: across tg (4 lanes) then across wn (4 warps) ----
    #pragma unroll
    for (int mt = 0; mt < 4; ++mt)
        #pragma unroll
        for (int d = 0; d < 2; ++d) {
            float v = bestv[mt][d];
            int   j = bestj[mt][d];
            #pragma unroll
            for (int off = 1; off <= 2; off <<= 1) {
                float vo = __shfl_xor_sync(0xffffffffu, v, off);
                int   jo = __shfl_xor_sync(0xffffffffu, j, off);
                if (vo < v || (vo == v && jo < j)) { v = vo; j = jo; }
            }
            if (tg == 0) {
                int row = wm * 64 + mt * 16 + g + d * 8;
                redv[row * 4 + wn] = v;
                redj[row * 4 + wn] = j;
            }
        }
    __syncthreads();
    if (tid < 128) {
        float v = redv[tid * 4];
        int   j = redj[tid * 4];
        #pragma unroll
        for (int w = 1; w < 4; ++w) {
            float v2 = redv[tid * 4 + w];
            int   j2 = redj[tid * 4 + w];
            if (v2 < v || (v2 == v && j2 < j)) { v = v2; j = j2; }
        }
        long p = base + tid;
        if (p < N) {
            g_assign[p] = j;
            out_assign[p] = (float)j;
        }
    }
}

// ---------------- scatter: segment sums via atomics ------------------------
__global__ void scatter_kernel(const float* __restrict__ F, int N) {
    int w = (blockIdx.x * blockDim.x + threadIdx.x) >> 5;
    int lane = threadIdx.x & 31;
    if (w >= N) return;
    int a = g_assign[w];
    float4 v = ((const float4*)(F + (size_t)w * DDIM))[lane];
    float* base = g_sums + a * DDIM + lane * 4;
    atomicAdd(base + 0, v.x);
    atomicAdd(base + 1, v.y);
    atomicAdd(base + 2, v.z);
    atomicAdd(base + 3, v.w);
    if (lane == 0) atomicAdd(&g_counts[a], 1);
}

// ---------------- finalize -------------------------------------------------
__global__ void finalize_kernel(float* __restrict__ out_centers) {
    int i = blockIdx.x * blockDim.x + threadIdx.x;
    if (i < KC * DDIM) {
        int k = i >> 7;
        float cnt = fmaxf((float)g_counts[k], 1.0f);
        out_centers[i] = g_sums[i] / cnt;
    }
}

// ---------------- launch ---------------------------------------------------
extern "C" void kernel_launch(void* const* d_in, const int* in_sizes, int n_in,
                              void* d_out, int out_size) {
    const float* F = (const float*)d_in[0];
    const float* C = (const float*)d_in[1];
    const int N = in_sizes[0] / DDIM;

    float* out = (float*)d_out;
    float* out_centers = out;
    float* out_assign  = out + KC * DDIM;

    prep_kernel<<<KC, DDIM>>>(C);
    bfrag_kernel<<<(3 * 4 * 8 * 16 * 32 * 2) / 256, 256>>>(C);

    const int smem_bytes = 98304 + 2048 + 2048 + 2048;   // 104448
    cudaFuncSetAttribute(assign_kernel,
                         cudaFuncAttributeMaxDynamicSharedMemorySize, smem_bytes);
    int grid = (N + 127) / 128;
    assign_kernel<<<grid, 256, smem_bytes>>>(F, N, out_assign);

    scatter_kernel<<<(N + 7) / 8, 256>>>(F, N);

    finalize_kernel<<<(KC * DDIM + 255) / 256, 256>>>(out_centers);
}

// round 6
// speedup vs baseline: 1.9830x; 1.5399x over previous
#include <cuda_runtime.h>
#include <cuda_bf16.h>
#include <cstdint>
#include <cstddef>

#define KC   512
#define DDIM 128
#define NMAX 200192

// ---------------- device scratch (no allocation allowed) -------------------
__device__ float    g_c2[KC];
__device__ float    g_sums[KC * DDIM];
__device__ int      g_counts[KC];
__device__ int      g_assign[NMAX];
// B fragments: [split(3)][ctile(4)][kstep(8)][ntile(16)][lane(32)][reg(2)]
__device__ uint32_t g_bfrag[3 * 4 * 8 * 16 * 32 * 2];   // 98304 u32 = 384 KB

// ---------------- helpers ---------------------------------------------------
__device__ __forceinline__ void split3f(float x, float& s0, float& s1, float& s2) {
    s0 = __bfloat162float(__float2bfloat16(x));
    float r = x - s0;
    s1 = __bfloat162float(__float2bfloat16(r));
    r -= s1;
    s2 = __bfloat162float(__float2bfloat16(r));
}
__device__ __forceinline__ uint32_t pack_bf(float lo, float hi) {
    __nv_bfloat16 l = __float2bfloat16(lo), h = __float2bfloat16(hi);
    uint16_t lb, hb;
    memcpy(&lb, &l, 2); memcpy(&hb, &h, 2);
    return (uint32_t)lb | ((uint32_t)hb << 16);
}
__device__ __forceinline__ void mma16816(float* d, const uint32_t* a, const uint32_t* b) {
    asm volatile(
        "mma.sync.aligned.m16n8k16.row.col.f32.bf16.bf16.f32 "
        "{%0,%1,%2,%3}, {%4,%5,%6,%7}, {%8,%9}, {%0,%1,%2,%3};"
        : "+f"(d[0]), "+f"(d[1]), "+f"(d[2]), "+f"(d[3])
        : "r"(a[0]), "r"(a[1]), "r"(a[2]), "r"(a[3]), "r"(b[0]), "r"(b[1]));
}
__device__ __forceinline__ void upd(float& bv, int& bj, float v, int j) {
    if (v < bv || (v == bv && j < bj)) { bv = v; bj = j; }
}
__device__ __forceinline__ void red_add_v4(float* gptr, float4 v) {
    asm volatile("red.global.add.v4.f32 [%0], {%1,%2,%3,%4};"
                 :: "l"(gptr), "f"(v.x), "f"(v.y), "f"(v.z), "f"(v.w)
                 : "memory");
}

// ---------------- prep: zero sums/counts, ||c||^2 --------------------------
__global__ void prep_kernel(const float* __restrict__ C) {
    int k = blockIdx.x, t = threadIdx.x;
    g_sums[k * DDIM + t] = 0.0f;
    if (t == 0) g_counts[k] = 0;
    float v = C[k * DDIM + t];
    v *= v;
    #pragma unroll
    for (int off = 16; off >= 1; off >>= 1) v += __shfl_down_sync(0xffffffffu, v, off);
    __shared__ float red[4];
    if ((t & 31) == 0) red[t >> 5] = v;
    __syncthreads();
    if (t == 0) g_c2[k] = (red[0] + red[1]) + (red[2] + red[3]);
}

// ---------------- prep: convert centers into B fragments -------------------
// mma.m16n8k16 B frag (col-major k x n): lane(g=l>>2,tg=l&3):
//   b0 = {B[k0+2tg][n0+g], B[k0+2tg+1][n0+g]}, b1 = same at k+8. low half = even k.
__global__ void bfrag_kernel(const float* __restrict__ C) {
    int idx = blockIdx.x * 256 + threadIdx.x;      // < 98304
    int r    = idx & 1;
    int lane = (idx >> 1) & 31;
    int nt   = (idx >> 6) & 15;
    int ks   = (idx >> 10) & 7;
    int ct   = (idx >> 13) & 3;
    int s    = idx >> 15;
    int g = lane >> 2, tg = lane & 3;
    int c = ct * 128 + nt * 8 + g;
    int k = ks * 16 + 2 * tg + r * 8;
    float x0 = C[c * DDIM + k], x1 = C[c * DDIM + k + 1];
    float a0, a1, a2, b0, b1, b2;
    split3f(x0, a0, a1, a2);
    split3f(x1, b0, b1, b2);
    float lo = (s == 0) ? a0 : ((s == 1) ? a1 : a2);
    float hi = (s == 0) ? b0 : ((s == 1) ? b1 : b2);
    g_bfrag[idx] = pack_bf(lo, hi);
}

// ---------------- fused bf16x3 HMMA GEMM + argmin + scatter ----------------
// CTA: 128 points x 512 centers. 8 warps, warp tile 64x32 per 128-center tile.
// smem: A fragments [split(3)][blk(64)=mtile*8+ks][lane(32)] x uint4 = 96 KB.
__global__ void __launch_bounds__(256, 1)
assign_kernel(const float* __restrict__ F, int N, float* __restrict__ out_assign) {
    extern __shared__ char smem[];
    uint32_t* As   = (uint32_t*)smem;              // 98304 B
    float*    c2s  = (float*)(smem + 98304);       // 2 KB
    float*    redv = (float*)(smem + 100352);      // 2 KB
    int*      redj = (int*)(smem + 102400);        // 2 KB (reused as final j)

    const int tid = threadIdx.x;
    const int lane = tid & 31, wid = tid >> 5;
    const int wm = wid >> 2, wn = wid & 3;
    const int g = lane >> 2, tg = lane & 3;
    const long base = (long)blockIdx.x * 128;

    c2s[tid]       = g_c2[tid];
    c2s[tid + 256] = g_c2[tid + 256];

    // ---- convert A (F tile) into fragment-ordered smem, 3 splits ----
    #pragma unroll
    for (int i = 0; i < 8; ++i) {
        int blk = (tid >> 5) + i * 8;              // 0..63: mtile*8 + ks
        int mt = blk >> 3, ks = blk & 7;
        long rA = base + mt * 16 + g;
        long rB = rA + 8;
        if (rA > (long)N - 1) rA = (long)N - 1;
        if (rB > (long)N - 1) rB = (long)N - 1;
        int kc = ks * 16 + 2 * tg;
        const float* F0 = F + (size_t)rA * DDIM;
        const float* F1 = F + (size_t)rB * DDIM;
        float2 p00 = *(const float2*)(F0 + kc);
        float2 p10 = *(const float2*)(F1 + kc);
        float2 p01 = *(const float2*)(F0 + kc + 8);
        float2 p11 = *(const float2*)(F1 + kc + 8);

        float x0[3], y0[3], x1[3], y1[3], x2[3], y2[3], x3[3], y3[3];
        split3f(p00.x, x0[0], x0[1], x0[2]); split3f(p00.y, y0[0], y0[1], y0[2]);
        split3f(p10.x, x1[0], x1[1], x1[2]); split3f(p10.y, y1[0], y1[1], y1[2]);
        split3f(p01.x, x2[0], x2[1], x2[2]); split3f(p01.y, y2[0], y2[1], y2[2]);
        split3f(p11.x, x3[0], x3[1], x3[2]); split3f(p11.y, y3[0], y3[1], y3[2]);

        #pragma unroll
        for (int s = 0; s < 3; ++s) {
            uint4 v;
            v.x = pack_bf(x0[s], y0[s]);
            v.y = pack_bf(x1[s], y1[s]);
            v.z = pack_bf(x2[s], y2[s]);
            v.w = pack_bf(x3[s], y3[s]);
            *(uint4*)(As + ((size_t)(s * 64 + blk) * 32 + lane) * 4) = v;
        }
    }
    __syncthreads();

    float bestv[4][2];
    int   bestj[4][2];
    #pragma unroll
    for (int mt = 0; mt < 4; ++mt)
        #pragma unroll
        for (int d = 0; d < 2; ++d) { bestv[mt][d] = 3.402823466e38f; bestj[mt][d] = 0x7fffffff; }

    const int CA[6] = {0, 0, 1, 1, 0, 2};
    const int CB[6] = {0, 1, 0, 1, 2, 0};

    for (int ct = 0; ct < 4; ++ct) {
        float acc[4][4][4];
        #pragma unroll
        for (int mt = 0; mt < 4; ++mt)
            #pragma unroll
            for (int nt = 0; nt < 4; ++nt)
                #pragma unroll
                for (int q = 0; q < 4; ++q) acc[mt][nt][q] = 0.0f;

        #pragma unroll 1
        for (int c = 0; c < 6; ++c) {
            const uint32_t* Abase = As + (size_t)CA[c] * 64 * 32 * 4;
            const uint32_t* Bbase = g_bfrag + (size_t)(CB[c] * 4 + ct) * 8 * 16 * 32 * 2;
            #pragma unroll
            for (int ks = 0; ks < 8; ++ks) {
                uint4 af[4];
                #pragma unroll
                for (int mt = 0; mt < 4; ++mt)
                    af[mt] = *(const uint4*)(Abase +
                        ((size_t)((wm * 4 + mt) * 8 + ks) * 32 + lane) * 4);
                uint2 bf[4];
                #pragma unroll
                for (int nt = 0; nt < 4; ++nt)
                    bf[nt] = *(const uint2*)(Bbase +
                        ((size_t)(ks * 16 + wn * 4 + nt) * 32 + lane) * 2);
                #pragma unroll
                for (int mt = 0; mt < 4; ++mt)
                    #pragma unroll
                    for (int nt = 0; nt < 4; ++nt)
                        mma16816(acc[mt][nt], (const uint32_t*)&af[mt], &bf[nt].x);
            }
        }

        // epilogue: score = c2 - 2*dot, fold into running argmin
        #pragma unroll
        for (int mt = 0; mt < 4; ++mt)
            #pragma unroll
            for (int nt = 0; nt < 4; ++nt) {
                int col = ct * 128 + wn * 32 + nt * 8 + 2 * tg;
                float c2a = c2s[col], c2b = c2s[col + 1];
                upd(bestv[mt][0], bestj[mt][0], fmaf(-2.0f, acc[mt][nt][0], c2a), col);
                upd(bestv[mt][0], bestj[mt][0], fmaf(-2.0f, acc[mt][nt][1], c2b), col + 1);
                upd(bestv[mt][1], bestj[mt][1], fmaf(-2.0f, acc[mt][nt][2], c2a), col);
                upd(bestv[mt][1], bestj[mt][1], fmaf(-2.0f, acc[mt][nt][3], c2b), col + 1);
            }
    }

    // ---- reduce: across tg (4 lanes) then across wn (4 warps) ----
    #pragma unroll
    for (int mt = 0; mt < 4; ++mt)
        #pragma unroll
        for (int d = 0; d < 2; ++d) {
            float v = bestv[mt][d];
            int   j = bestj[mt][d];
            #pragma unroll
            for (int off = 1; off <= 2; off <<= 1) {
                float vo = __shfl_xor_sync(0xffffffffu, v, off);
                int   jo = __shfl_xor_sync(0xffffffffu, j, off);
                if (vo < v || (vo == v && jo < j)) { v = vo; j = jo; }
            }
            if (tg == 0) {
                int row = wm * 64 + mt * 16 + g + d * 8;
                redv[row * 4 + wn] = v;
                redj[row * 4 + wn] = j;
            }
        }
    __syncthreads();

    int* sj = redj + 512;   // careful: redj block is 2KB = 512 ints; reuse redv area
    // use a dedicated slot: store final j into redv reinterpreted (after sync)
    if (tid < 128) {
        float v = redv[tid * 4];
        int   j = redj[tid * 4];
        #pragma unroll
        for (int w = 1; w < 4; ++w) {
            float v2 = redv[tid * 4 + w];
            int   j2 = redj[tid * 4 + w];
            if (v2 < v || (v2 == v && j2 < j)) { v = v2; j = j2; }
        }
        long p = base + tid;
        if (p < N) {
            g_assign[p] = j;
            out_assign[p] = (float)j;
            atomicAdd(&g_counts[j], 1);     // RED (result unused)
        }
        ((int*)redv)[tid] = j;              // publish for scatter phase
    }
    __syncthreads();
    (void)sj;

    // ---- fused scatter: red.v4 of F rows into g_sums ----
    const int npts = (int)((base + 128 <= (long)N) ? 128 : (N - base));
    const int* jarr = (const int*)redv;
    for (int i = tid; i < npts * 32; i += 256) {
        int pt = i >> 5;
        int ch = i & 31;
        float4 v = ((const float4*)(F + (size_t)(base + pt) * DDIM))[ch];
        red_add_v4(g_sums + (size_t)jarr[pt] * DDIM + ch * 4, v);
    }
}

// ---------------- finalize -------------------------------------------------
__global__ void finalize_kernel(float* __restrict__ out_centers) {
    int i = blockIdx.x * blockDim.x + threadIdx.x;
    if (i < KC * DDIM) {
        int k = i >> 7;
        float cnt = fmaxf((float)g_counts[k], 1.0f);
        out_centers[i] = g_sums[i] / cnt;
    }
}

// ---------------- launch ---------------------------------------------------
extern "C" void kernel_launch(void* const* d_in, const int* in_sizes, int n_in,
                              void* d_out, int out_size) {
    const float* F = (const float*)d_in[0];
    const float* C = (const float*)d_in[1];
    const int N = in_sizes[0] / DDIM;

    float* out = (float*)d_out;
    float* out_centers = out;
    float* out_assign  = out + KC * DDIM;

    prep_kernel<<<KC, DDIM>>>(C);
    bfrag_kernel<<<(3 * 4 * 8 * 16 * 32 * 2) / 256, 256>>>(C);

    const int smem_bytes = 98304 + 2048 + 2048 + 2048;   // 104448
    cudaFuncSetAttribute(assign_kernel,
                         cudaFuncAttributeMaxDynamicSharedMemorySize, smem_bytes);
    int grid = (N + 127) / 128;
    assign_kernel<<<grid, 256, smem_bytes>>>(F, N, out_assign);

    finalize_kernel<<<(KC * DDIM + 255) / 256, 256>>>(out_centers);
}

// round 7
// speedup vs baseline: 2.2278x; 1.1235x over previous
#include <cuda_runtime.h>
#include <cuda_bf16.h>
#include <cstdint>
#include <cstddef>

#define KC   512
#define DDIM 128
#define NMAX 200192

// ---------------- device scratch (no allocation allowed) -------------------
__device__ float    g_c2[KC];
__device__ float    g_sums[KC * DDIM];
__device__ int      g_counts[KC];
__device__ int      g_assign[NMAX];
// B fragments: [split(3)][ctile(4)][kstep(8)][ntile(16)][lane(32)][reg(2)]
__device__ uint32_t g_bfrag[3 * 4 * 8 * 16 * 32 * 2];   // 98304 u32 = 384 KB

// ---------------- helpers ---------------------------------------------------
__device__ __forceinline__ void split3f(float x, float& s0, float& s1, float& s2) {
    s0 = __bfloat162float(__float2bfloat16(x));
    float r = x - s0;
    s1 = __bfloat162float(__float2bfloat16(r));
    r -= s1;
    s2 = __bfloat162float(__float2bfloat16(r));
}
__device__ __forceinline__ uint32_t pack_bf(float lo, float hi) {
    __nv_bfloat16 l = __float2bfloat16(lo), h = __float2bfloat16(hi);
    uint16_t lb, hb;
    memcpy(&lb, &l, 2); memcpy(&hb, &h, 2);
    return (uint32_t)lb | ((uint32_t)hb << 16);
}
__device__ __forceinline__ void mma16816(float* d, const uint32_t* a, const uint32_t* b) {
    asm volatile(
        "mma.sync.aligned.m16n8k16.row.col.f32.bf16.bf16.f32 "
        "{%0,%1,%2,%3}, {%4,%5,%6,%7}, {%8,%9}, {%0,%1,%2,%3};"
        : "+f"(d[0]), "+f"(d[1]), "+f"(d[2]), "+f"(d[3])
        : "r"(a[0]), "r"(a[1]), "r"(a[2]), "r"(a[3]), "r"(b[0]), "r"(b[1]));
}
__device__ __forceinline__ void upd(float& bv, int& bj, float v, int j) {
    if (v < bv || (v == bv && j < bj)) { bv = v; bj = j; }
}
__device__ __forceinline__ void red_add_v4(float* gptr, float4 v) {
    asm volatile("red.global.add.v4.f32 [%0], {%1,%2,%3,%4};"
                 :: "l"(gptr), "f"(v.x), "f"(v.y), "f"(v.z), "f"(v.w)
                 : "memory");
}

// ---------------- prep: zero sums/counts, ||c||^2 --------------------------
__global__ void prep_kernel(const float* __restrict__ C) {
    int k = blockIdx.x, t = threadIdx.x;
    g_sums[k * DDIM + t] = 0.0f;
    if (t == 0) g_counts[k] = 0;
    float v = C[k * DDIM + t];
    v *= v;
    #pragma unroll
    for (int off = 16; off >= 1; off >>= 1) v += __shfl_down_sync(0xffffffffu, v, off);
    __shared__ float red[4];
    if ((t & 31) == 0) red[t >> 5] = v;
    __syncthreads();
    if (t == 0) g_c2[k] = (red[0] + red[1]) + (red[2] + red[3]);
}

// ---------------- prep: convert centers into B fragments -------------------
__global__ void bfrag_kernel(const float* __restrict__ C) {
    int idx = blockIdx.x * 256 + threadIdx.x;      // < 98304
    int r    = idx & 1;
    int lane = (idx >> 1) & 31;
    int nt   = (idx >> 6) & 15;
    int ks   = (idx >> 10) & 7;
    int ct   = (idx >> 13) & 3;
    int s    = idx >> 15;
    int g = lane >> 2, tg = lane & 3;
    int c = ct * 128 + nt * 8 + g;
    int k = ks * 16 + 2 * tg + r * 8;
    float x0 = C[c * DDIM + k], x1 = C[c * DDIM + k + 1];
    float a0, a1, a2, b0, b1, b2;
    split3f(x0, a0, a1, a2);
    split3f(x1, b0, b1, b2);
    float lo = (s == 0) ? a0 : ((s == 1) ? a1 : a2);
    float hi = (s == 0) ? b0 : ((s == 1) ? b1 : b2);
    g_bfrag[idx] = pack_bf(lo, hi);
}

// ---------------- fused bf16x3 HMMA GEMM + argmin + scatter ----------------
// CTA: 128 points x 512 centers. 8 warps, warp tile 64x32 per 128-center tile.
// smem: A fragments [split(3)][blk(64)=mtile*8+ks][lane(32)] x uint4 = 96 KB.
// Mainloop: ks outer, 6 split-combos inner (96 HMMA per ks), B prefetched.
__global__ void __launch_bounds__(256, 1)
assign_kernel(const float* __restrict__ F, int N, float* __restrict__ out_assign) {
    extern __shared__ char smem[];
    uint32_t* As   = (uint32_t*)smem;              // 98304 B
    float*    c2s  = (float*)(smem + 98304);       // 2 KB
    float*    redv = (float*)(smem + 100352);      // 2 KB
    int*      redj = (int*)(smem + 102400);        // 2 KB

    const int tid = threadIdx.x;
    const int lane = tid & 31, wid = tid >> 5;
    const int wm = wid >> 2, wn = wid & 3;
    const int g = lane >> 2, tg = lane & 3;
    const long base = (long)blockIdx.x * 128;

    c2s[tid]       = g_c2[tid];
    c2s[tid + 256] = g_c2[tid + 256];

    // ---- convert A (F tile) into fragment-ordered smem, 3 splits ----
    #pragma unroll
    for (int i = 0; i < 8; ++i) {
        int blk = (tid >> 5) + i * 8;              // 0..63: mtile*8 + ks
        int mt = blk >> 3, ks = blk & 7;
        long rA = base + mt * 16 + g;
        long rB = rA + 8;
        if (rA > (long)N - 1) rA = (long)N - 1;
        if (rB > (long)N - 1) rB = (long)N - 1;
        int kc = ks * 16 + 2 * tg;
        const float* F0 = F + (size_t)rA * DDIM;
        const float* F1 = F + (size_t)rB * DDIM;
        float2 p00 = *(const float2*)(F0 + kc);
        float2 p10 = *(const float2*)(F1 + kc);
        float2 p01 = *(const float2*)(F0 + kc + 8);
        float2 p11 = *(const float2*)(F1 + kc + 8);

        float x0[3], y0[3], x1[3], y1[3], x2[3], y2[3], x3[3], y3[3];
        split3f(p00.x, x0[0], x0[1], x0[2]); split3f(p00.y, y0[0], y0[1], y0[2]);
        split3f(p10.x, x1[0], x1[1], x1[2]); split3f(p10.y, y1[0], y1[1], y1[2]);
        split3f(p01.x, x2[0], x2[1], x2[2]); split3f(p01.y, y2[0], y2[1], y2[2]);
        split3f(p11.x, x3[0], x3[1], x3[2]); split3f(p11.y, y3[0], y3[1], y3[2]);

        #pragma unroll
        for (int s = 0; s < 3; ++s) {
            uint4 v;
            v.x = pack_bf(x0[s], y0[s]);
            v.y = pack_bf(x1[s], y1[s]);
            v.z = pack_bf(x2[s], y2[s]);
            v.w = pack_bf(x3[s], y3[s]);
            *(uint4*)(As + ((size_t)(s * 64 + blk) * 32 + lane) * 4) = v;
        }
    }
    __syncthreads();

    float bestv[4][2];
    int   bestj[4][2];
    #pragma unroll
    for (int mt = 0; mt < 4; ++mt)
        #pragma unroll
        for (int d = 0; d < 2; ++d) { bestv[mt][d] = 3.402823466e38f; bestj[mt][d] = 0x7fffffff; }

    // combo order grouped by A-split: a0*(b0,b1,b2), a1*(b0,b1), a2*b0
    const int NCMB[3] = {3, 2, 1};   // #b-splits per a-split

    for (int ct = 0; ct < 4; ++ct) {
        float acc[4][4][4];
        #pragma unroll
        for (int mt = 0; mt < 4; ++mt)
            #pragma unroll
            for (int nt = 0; nt < 4; ++nt)
                #pragma unroll
                for (int q = 0; q < 4; ++q) acc[mt][nt][q] = 0.0f;

        // per-(split,ct) B fragment bases for this warp's n-columns
        const uint32_t* Bb[3];
        #pragma unroll
        for (int s = 0; s < 3; ++s)
            Bb[s] = g_bfrag + (size_t)(s * 4 + ct) * 8 * 16 * 32 * 2
                  + ((size_t)(wn * 4) * 32 + lane) * 2;

        // prefetch B splits for ks=0
        uint2 bf[3][4];
        #pragma unroll
        for (int s = 0; s < 3; ++s)
            #pragma unroll
            for (int nt = 0; nt < 4; ++nt)
                bf[s][nt] = *(const uint2*)(Bb[s] + (size_t)nt * 32 * 2);

        #pragma unroll
        for (int ks = 0; ks < 8; ++ks) {
            // prefetch B for ks+1 (hidden under the 96-HMMA body)
            uint2 bfn[3][4];
            if (ks < 7) {
                #pragma unroll
                for (int s = 0; s < 3; ++s)
                    #pragma unroll
                    for (int nt = 0; nt < 4; ++nt)
                        bfn[s][nt] = *(const uint2*)(Bb[s] +
                            ((size_t)(ks + 1) * 16 + nt) * 32 * 2);
            }

            // for each A-split: 4 LDS.128 then its combo group's MMAs
            #pragma unroll
            for (int sa = 0; sa < 3; ++sa) {
                uint4 af[4];
                #pragma unroll
                for (int mt = 0; mt < 4; ++mt)
                    af[mt] = *(const uint4*)(As +
                        ((size_t)(sa * 64 + (wm * 4 + mt) * 8 + ks) * 32 + lane) * 4);
                #pragma unroll
                for (int sb = 0; sb < 3; ++sb) {
                    if (sb >= NCMB[sa]) break;
                    #pragma unroll
                    for (int mt = 0; mt < 4; ++mt)
                        #pragma unroll
                        for (int nt = 0; nt < 4; ++nt)
                            mma16816(acc[mt][nt], (const uint32_t*)&af[mt],
                                     &bf[sb][nt].x);
                }
            }

            #pragma unroll
            for (int s = 0; s < 3; ++s)
                #pragma unroll
                for (int nt = 0; nt < 4; ++nt)
                    bf[s][nt] = bfn[s][nt];
        }

        // epilogue: score = c2 - 2*dot, fold into running argmin
        #pragma unroll
        for (int mt = 0; mt < 4; ++mt)
            #pragma unroll
            for (int nt = 0; nt < 4; ++nt) {
                int col = ct * 128 + wn * 32 + nt * 8 + 2 * tg;
                float c2a = c2s[col], c2b = c2s[col + 1];
                upd(bestv[mt][0], bestj[mt][0], fmaf(-2.0f, acc[mt][nt][0], c2a), col);
                upd(bestv[mt][0], bestj[mt][0], fmaf(-2.0f, acc[mt][nt][1], c2b), col + 1);
                upd(bestv[mt][1], bestj[mt][1], fmaf(-2.0f, acc[mt][nt][2], c2a), col);
                upd(bestv[mt][1], bestj[mt][1], fmaf(-2.0f, acc[mt][nt][3], c2b), col + 1);
            }
    }

    // ---- reduce: across tg (4 lanes) then across wn (4 warps) ----
    #pragma unroll
    for (int mt = 0; mt < 4; ++mt)
        #pragma unroll
        for (int d = 0; d < 2; ++d) {
            float v = bestv[mt][d];
            int   j = bestj[mt][d];
            #pragma unroll
            for (int off = 1; off <= 2; off <<= 1) {
                float vo = __shfl_xor_sync(0xffffffffu, v, off);
                int   jo = __shfl_xor_sync(0xffffffffu, j, off);
                if (vo < v || (vo == v && jo < j)) { v = vo; j = jo; }
            }
            if (tg == 0) {
                int row = wm * 64 + mt * 16 + g + d * 8;
                redv[row * 4 + wn] = v;
                redj[row * 4 + wn] = j;
            }
        }
    __syncthreads();

    if (tid < 128) {
        float v = redv[tid * 4];
        int   j = redj[tid * 4];
        #pragma unroll
        for (int w = 1; w < 4; ++w) {
            float v2 = redv[tid * 4 + w];
            int   j2 = redj[tid * 4 + w];
            if (v2 < v || (v2 == v && j2 < j)) { v = v2; j = j2; }
        }
        long p = base + tid;
        if (p < N) {
            g_assign[p] = j;
            out_assign[p] = (float)j;
            atomicAdd(&g_counts[j], 1);
        }
        redj[tid] = j;              // publish for scatter phase
    }
    __syncthreads();

    // ---- fused scatter: red.v4 of F rows into g_sums ----
    const int npts = (int)((base + 128 <= (long)N) ? 128 : (N - base));
    for (int i = tid; i < npts * 32; i += 256) {
        int pt = i >> 5;
        int ch = i & 31;
        float4 v = ((const float4*)(F + (size_t)(base + pt) * DDIM))[ch];
        red_add_v4(g_sums + (size_t)redj[pt] * DDIM + ch * 4, v);
    }
}

// ---------------- finalize -------------------------------------------------
__global__ void finalize_kernel(float* __restrict__ out_centers) {
    int i = blockIdx.x * blockDim.x + threadIdx.x;
    if (i < KC * DDIM) {
        int k = i >> 7;
        float cnt = fmaxf((float)g_counts[k], 1.0f);
        out_centers[i] = g_sums[i] / cnt;
    }
}

// ---------------- launch ---------------------------------------------------
extern "C" void kernel_launch(void* const* d_in, const int* in_sizes, int n_in,
                              void* d_out, int out_size) {
    const float* F = (const float*)d_in[0];
    const float* C = (const float*)d_in[1];
    const int N = in_sizes[0] / DDIM;

    float* out = (float*)d_out;
    float* out_centers = out;
    float* out_assign  = out + KC * DDIM;

    prep_kernel<<<KC, DDIM>>>(C);
    bfrag_kernel<<<(3 * 4 * 8 * 16 * 32 * 2) / 256, 256>>>(C);

    const int smem_bytes = 98304 + 2048 + 2048 + 2048;   // 104448
    cudaFuncSetAttribute(assign_kernel,
                         cudaFuncAttributeMaxDynamicSharedMemorySize, smem_bytes);
    int grid = (N + 127) / 128;
    assign_kernel<<<grid, 256, smem_bytes>>>(F, N, out_assign);

    finalize_kernel<<<(KC * DDIM + 255) / 256, 256>>>(out_centers);
}

// round 9
// speedup vs baseline: 3.6235x; 1.6265x over previous
#include <cuda_runtime.h>
#include <cuda_fp16.h>
#include <cstdint>
#include <cstddef>

#define KC   512
#define DDIM 128
#define NMAX 200192

// ---------------- device scratch (no allocation allowed) -------------------
__device__ float    g_c2[KC];
__device__ float    g_sums[KC * DDIM];
__device__ int      g_counts[KC];
__device__ int      g_assign[NMAX];
// B fragments: [split(2)][ctile(4)][kstep(8)][ntile(16)][lane(32)][reg(2)]
__device__ uint32_t g_bfrag[2 * 4 * 8 * 16 * 32 * 2];   // 65536 u32 = 256 KB

// ---------------- helpers ---------------------------------------------------
__device__ __forceinline__ void split2h(float x, float& s0, float& s1) {
    s0 = __half2float(__float2half_rn(x));
    s1 = x - s0;                       // exact in fp32; fp16(s1) carries 11 more bits
}
__device__ __forceinline__ uint32_t pack_h2(float lo, float hi) {
    __half l = __float2half_rn(lo), h = __float2half_rn(hi);
    uint16_t lb, hb;
    memcpy(&lb, &l, 2); memcpy(&hb, &h, 2);
    return (uint32_t)lb | ((uint32_t)hb << 16);
}
__device__ __forceinline__ void mma16816(float* d, const uint32_t* a, const uint32_t* b) {
    asm volatile(
        "mma.sync.aligned.m16n8k16.row.col.f32.f16.f16.f32 "
        "{%0,%1,%2,%3}, {%4,%5,%6,%7}, {%8,%9}, {%0,%1,%2,%3};"
        : "+f"(d[0]), "+f"(d[1]), "+f"(d[2]), "+f"(d[3])
        : "r"(a[0]), "r"(a[1]), "r"(a[2]), "r"(a[3]), "r"(b[0]), "r"(b[1]));
}
__device__ __forceinline__ void upd(float& bv, int& bj, float v, int j) {
    if (v < bv || (v == bv && j < bj)) { bv = v; bj = j; }
}
__device__ __forceinline__ void red_add_v4(float* gptr, float4 v) {
    asm volatile("red.global.add.v4.f32 [%0], {%1,%2,%3,%4};"
                 :: "l"(gptr), "f"(v.x), "f"(v.y), "f"(v.z), "f"(v.w)
                 : "memory");
}

// ---------------- prep: zero sums/counts, ||c||^2 --------------------------
__global__ void prep_kernel(const float* __restrict__ C) {
    int k = blockIdx.x, t = threadIdx.x;
    g_sums[k * DDIM + t] = 0.0f;
    if (t == 0) g_counts[k] = 0;
    float v = C[k * DDIM + t];
    v *= v;
    #pragma unroll
    for (int off = 16; off >= 1; off >>= 1) v += __shfl_down_sync(0xffffffffu, v, off);
    __shared__ float red[4];
    if ((t & 31) == 0) red[t >> 5] = v;
    __syncthreads();
    if (t == 0) g_c2[k] = (red[0] + red[1]) + (red[2] + red[3]);
}

// ---------------- prep: convert centers into B fragments (fp16 x2) ---------
// mma.m16n8k16 B frag (col-major k x n): lane(g=l>>2,tg=l&3):
//   b0 = {B[k0+2tg][n0+g], B[k0+2tg+1][n0+g]}, b1 = same at k+8.
__global__ void bfrag_kernel(const float* __restrict__ C) {
    int idx = blockIdx.x * 256 + threadIdx.x;      // < 65536
    int r    = idx & 1;
    int lane = (idx >> 1) & 31;
    int nt   = (idx >> 6) & 15;
    int ks   = (idx >> 10) & 7;
    int ct   = (idx >> 13) & 3;
    int s    = idx >> 15;                          // 0..1
    int g = lane >> 2, tg = lane & 3;
    int c = ct * 128 + nt * 8 + g;
    int k = ks * 16 + 2 * tg + r * 8;
    float x0 = C[c * DDIM + k], x1 = C[c * DDIM + k + 1];
    float a0, a1, b0, b1;
    split2h(x0, a0, a1);
    split2h(x1, b0, b1);
    float lo = (s == 0) ? a0 : a1;
    float hi = (s == 0) ? b0 : b1;
    g_bfrag[idx] = pack_h2(lo, hi);
}

// ---------------- fused fp16x2 HMMA GEMM + argmin + scatter ----------------
// CTA: 128 points x 512 centers. 8 warps, warp tile 64x32 per 128-center tile.
// smem: A fragments [split(2)][blk(64)=mtile*8+ks][lane(32)] x uint4 = 64 KB.
// Mainloop: ks outer, 3 split-combos (h0*g0, h0*g1, h1*g0) = 48 HMMA per ks.
__global__ void __launch_bounds__(256, 1)
assign_kernel(const float* __restrict__ F, int N, float* __restrict__ out_assign) {
    extern __shared__ char smem[];
    uint32_t* As   = (uint32_t*)smem;              // 65536 B
    float*    c2s  = (float*)(smem + 65536);       // 2 KB
    float*    redv = (float*)(smem + 67584);       // 2 KB
    int*      redj = (int*)(smem + 69632);         // 2 KB

    const int tid = threadIdx.x;
    const int lane = tid & 31, wid = tid >> 5;
    const int wm = wid >> 2, wn = wid & 3;
    const int g = lane >> 2, tg = lane & 3;
    const long base = (long)blockIdx.x * 128;

    c2s[tid]       = g_c2[tid];
    c2s[tid + 256] = g_c2[tid + 256];

    // ---- convert A (F tile) into fragment-ordered smem, 2 splits ----
    #pragma unroll
    for (int i = 0; i < 8; ++i) {
        int blk = (tid >> 5) + i * 8;              // 0..63: mtile*8 + ks
        int mt = blk >> 3, ks = blk & 7;
        long rA = base + mt * 16 + g;
        long rB = rA + 8;
        if (rA > (long)N - 1) rA = (long)N - 1;
        if (rB > (long)N - 1) rB = (long)N - 1;
        int kc = ks * 16 + 2 * tg;
        const float* F0 = F + (size_t)rA * DDIM;
        const float* F1 = F + (size_t)rB * DDIM;
        float2 p00 = *(const float2*)(F0 + kc);
        float2 p10 = *(const float2*)(F1 + kc);
        float2 p01 = *(const float2*)(F0 + kc + 8);
        float2 p11 = *(const float2*)(F1 + kc + 8);

        float x0[2], y0[2], x1[2], y1[2], x2[2], y2[2], x3[2], y3[2];
        split2h(p00.x, x0[0], x0[1]); split2h(p00.y, y0[0], y0[1]);
        split2h(p10.x, x1[0], x1[1]); split2h(p10.y, y1[0], y1[1]);
        split2h(p01.x, x2[0], x2[1]); split2h(p01.y, y2[0], y2[1]);
        split2h(p11.x, x3[0], x3[1]); split2h(p11.y, y3[0], y3[1]);

        #pragma unroll
        for (int s = 0; s < 2; ++s) {
            uint4 v;
            v.x = pack_h2(x0[s], y0[s]);
            v.y = pack_h2(x1[s], y1[s]);
            v.z = pack_h2(x2[s], y2[s]);
            v.w = pack_h2(x3[s], y3[s]);
            *(uint4*)(As + ((size_t)(s * 64 + blk) * 32 + lane) * 4) = v;
        }
    }
    __syncthreads();

    float bestv[4][2];
    int   bestj[4][2];
    #pragma unroll
    for (int mt = 0; mt < 4; ++mt)
        #pragma unroll
        for (int d = 0; d < 2; ++d) { bestv[mt][d] = 3.402823466e38f; bestj[mt][d] = 0x7fffffff; }

    // combos grouped by A-split: h0*(g0,g1), h1*g0
    const int NCMB[2] = {2, 1};

    for (int ct = 0; ct < 4; ++ct) {
        float acc[4][4][4];
        #pragma unroll
        for (int mt = 0; mt < 4; ++mt)
            #pragma unroll
            for (int nt = 0; nt < 4; ++nt)
                #pragma unroll
                for (int q = 0; q < 4; ++q) acc[mt][nt][q] = 0.0f;

        const uint32_t* Bb[2];
        #pragma unroll
        for (int s = 0; s < 2; ++s)
            Bb[s] = g_bfrag + (size_t)(s * 4 + ct) * 8 * 16 * 32 * 2
                  + ((size_t)(wn * 4) * 32 + lane) * 2;

        // prefetch B splits for ks=0
        uint2 bf[2][4];
        #pragma unroll
        for (int s = 0; s < 2; ++s)
            #pragma unroll
            for (int nt = 0; nt < 4; ++nt)
                bf[s][nt] = *(const uint2*)(Bb[s] + (size_t)nt * 32 * 2);

        #pragma unroll
        for (int ks = 0; ks < 8; ++ks) {
            // prefetch B for ks+1 (hidden under the 48-HMMA body)
            uint2 bfn[2][4];
            if (ks < 7) {
                #pragma unroll
                for (int s = 0; s < 2; ++s)
                    #pragma unroll
                    for (int nt = 0; nt < 4; ++nt)
                        bfn[s][nt] = *(const uint2*)(Bb[s] +
                            ((size_t)(ks + 1) * 16 + nt) * 32 * 2);
            }

            // hoist ALL A-split loads for this ks (8 LDS.128)
            uint4 af[2][4];
            #pragma unroll
            for (int sa = 0; sa < 2; ++sa)
                #pragma unroll
                for (int mt = 0; mt < 4; ++mt)
                    af[sa][mt] = *(const uint4*)(As +
                        ((size_t)(sa * 64 + (wm * 4 + mt) * 8 + ks) * 32 + lane) * 4);

            #pragma unroll
            for (int sa = 0; sa < 2; ++sa)
                #pragma unroll
                for (int sb = 0; sb < 2; ++sb) {
                    if (sb >= NCMB[sa]) break;
                    #pragma unroll
                    for (int mt = 0; mt < 4; ++mt)
                        #pragma unroll
                        for (int nt = 0; nt < 4; ++nt)
                            mma16816(acc[mt][nt], (const uint32_t*)&af[sa][mt],
                                     &bf[sb][nt].x);
                }

            #pragma unroll
            for (int s = 0; s < 2; ++s)
                #pragma unroll
                for (int nt = 0; nt < 4; ++nt)
                    bf[s][nt] = bfn[s][nt];
        }

        // epilogue: score = c2 - 2*dot, fold into running argmin
        #pragma unroll
        for (int mt = 0; mt < 4; ++mt)
            #pragma unroll
            for (int nt = 0; nt < 4; ++nt) {
                int col = ct * 128 + wn * 32 + nt * 8 + 2 * tg;
                float c2a = c2s[col], c2b = c2s[col + 1];
                upd(bestv[mt][0], bestj[mt][0], fmaf(-2.0f, acc[mt][nt][0], c2a), col);
                upd(bestv[mt][0], bestj[mt][0], fmaf(-2.0f, acc[mt][nt][1], c2b), col + 1);
                upd(bestv[mt][1], bestj[mt][1], fmaf(-2.0f, acc[mt][nt][2], c2a), col);
                upd(bestv[mt][1], bestj[mt][1], fmaf(-2.0f, acc[mt][nt][3], c2b), col + 1);
            }
    }

    // ---- reduce: across tg (4 lanes) then across wn (4 warps) ----
    #pragma unroll
    for (int mt = 0; mt < 4; ++mt)
        #pragma unroll
        for (int d = 0; d < 2; ++d) {
            float v = bestv[mt][d];
            int   j = bestj[mt][d];
            #pragma unroll
            for (int off = 1; off <= 2; off <<= 1) {
                float vo = __shfl_xor_sync(0xffffffffu, v, off);
                int   jo = __shfl_xor_sync(0xffffffffu, j, off);
                if (vo < v || (vo == v && jo < j)) { v = vo; j = jo; }
            }
            if (tg == 0) {
                int row = wm * 64 + mt * 16 + g + d * 8;
                redv[row * 4 + wn] = v;
                redj[row * 4 + wn] = j;
            }
        }
    __syncthreads();

    if (tid < 128) {
        float v = redv[tid * 4];
        int   j = redj[tid * 4];
        #pragma unroll
        for (int w = 1; w < 4; ++w) {
            float v2 = redv[tid * 4 + w];
            int   j2 = redj[tid * 4 + w];
            if (v2 < v || (v2 == v && j2 < j)) { v = v2; j = j2; }
        }
        long p = base + tid;
        if (p < N) {
            g_assign[p] = j;
            out_assign[p] = (float)j;
            atomicAdd(&g_counts[j], 1);
        }
        redj[tid] = j;              // publish for scatter phase
    }
    __syncthreads();

    // ---- fused scatter: red.v4 of F rows into g_sums ----
    const int npts = (int)((base + 128 <= (long)N) ? 128 : (N - base));
    for (int i = tid; i < npts * 32; i += 256) {
        int pt = i >> 5;
        int ch = i & 31;
        float4 v = ((const float4*)(F + (size_t)(base + pt) * DDIM))[ch];
        red_add_v4(g_sums + (size_t)redj[pt] * DDIM + ch * 4, v);
    }
}

// ---------------- finalize -------------------------------------------------
__global__ void finalize_kernel(float* __restrict__ out_centers) {
    int i = blockIdx.x * blockDim.x + threadIdx.x;
    if (i < KC * DDIM) {
        int k = i >> 7;
        float cnt = fmaxf((float)g_counts[k], 1.0f);
        out_centers[i] = g_sums[i] / cnt;
    }
}

// ---------------- launch ---------------------------------------------------
extern "C" void kernel_launch(void* const* d_in, const int* in_sizes, int n_in,
                              void* d_out, int out_size) {
    const float* F = (const float*)d_in[0];
    const float* C = (const float*)d_in[1];
    const int N = in_sizes[0] / DDIM;

    float* out = (float*)d_out;
    float* out_centers = out;
    float* out_assign  = out + KC * DDIM;

    prep_kernel<<<KC, DDIM>>>(C);
    bfrag_kernel<<<(2 * 4 * 8 * 16 * 32 * 2) / 256, 256>>>(C);

    const int smem_bytes = 65536 + 2048 + 2048 + 2048;   // 71680
    cudaFuncSetAttribute(assign_kernel,
                         cudaFuncAttributeMaxDynamicSharedMemorySize, smem_bytes);
    int grid = (N + 127) / 128;
    assign_kernel<<<grid, 256, smem_bytes>>>(F, N, out_assign);

    finalize_kernel<<<(KC * DDIM + 255) / 256, 256>>>(out_centers);
}

// round 10
// speedup vs baseline: 3.6532x; 1.0082x over previous
#include <cuda_runtime.h>
#include <cuda_fp16.h>
#include <cstdint>
#include <cstddef>

#define KC   512
#define DDIM 128
#define NMAX 200192

// ---------------- device scratch (no allocation allowed) -------------------
__device__ float    g_c2[KC];
__device__ float    g_sums[KC * DDIM];
__device__ int      g_counts[KC];
__device__ int      g_tilectr;
// B fragments: [split(2)][ctile(4)][kstep(8)][ntile(16)][lane(32)][reg(2)]
__device__ uint32_t g_bfrag[2 * 4 * 8 * 16 * 32 * 2];   // 65536 u32 = 256 KB

// ---------------- helpers ---------------------------------------------------
__device__ __forceinline__ void split2h(float x, float& s0, float& s1) {
    s0 = __half2float(__float2half_rn(x));
    s1 = x - s0;                       // exact in fp32; fp16(s1) carries 11 more bits
}
__device__ __forceinline__ uint32_t pack_h2(float lo, float hi) {
    __half l = __float2half_rn(lo), h = __float2half_rn(hi);
    uint16_t lb, hb;
    memcpy(&lb, &l, 2); memcpy(&hb, &h, 2);
    return (uint32_t)lb | ((uint32_t)hb << 16);
}
__device__ __forceinline__ void mma16816(float* d, const uint32_t* a, const uint32_t* b) {
    asm volatile(
        "mma.sync.aligned.m16n8k16.row.col.f32.f16.f16.f32 "
        "{%0,%1,%2,%3}, {%4,%5,%6,%7}, {%8,%9}, {%0,%1,%2,%3};"
        : "+f"(d[0]), "+f"(d[1]), "+f"(d[2]), "+f"(d[3])
        : "r"(a[0]), "r"(a[1]), "r"(a[2]), "r"(a[3]), "r"(b[0]), "r"(b[1]));
}
__device__ __forceinline__ void upd(float& bv, int& bj, float v, int j) {
    if (v < bv || (v == bv && j < bj)) { bv = v; bj = j; }
}
__device__ __forceinline__ void red_add_v4(float* gptr, float4 v) {
    asm volatile("red.global.add.v4.f32 [%0], {%1,%2,%3,%4};"
                 :: "l"(gptr), "f"(v.x), "f"(v.y), "f"(v.z), "f"(v.w)
                 : "memory");
}

// ---------------- prep (fused): zero sums/counts/ctr, ||c||^2, B frags -----
// 512 blocks x 128 threads; bfrag item index = blockIdx.x*128 + tid (65536).
__global__ void prep_kernel(const float* __restrict__ C) {
    int k = blockIdx.x, t = threadIdx.x;
    g_sums[k * DDIM + t] = 0.0f;
    if (t == 0) g_counts[k] = 0;
    if (k == 0 && t == 0) g_tilectr = 0;

    // ||c_k||^2
    float v = C[k * DDIM + t];
    v *= v;
    #pragma unroll
    for (int off = 16; off >= 1; off >>= 1) v += __shfl_down_sync(0xffffffffu, v, off);
    __shared__ float red[4];
    if ((t & 31) == 0) red[t >> 5] = v;
    __syncthreads();
    if (t == 0) g_c2[k] = (red[0] + red[1]) + (red[2] + red[3]);

    // B fragment conversion (fp16 x2)
    int idx = k * 128 + t;                         // < 65536
    int r    = idx & 1;
    int lane = (idx >> 1) & 31;
    int nt   = (idx >> 6) & 15;
    int ks   = (idx >> 10) & 7;
    int ct   = (idx >> 13) & 3;
    int s    = idx >> 15;                          // 0..1
    int g = lane >> 2, tg = lane & 3;
    int c = ct * 128 + nt * 8 + g;
    int kk = ks * 16 + 2 * tg + r * 8;
    float x0 = C[c * DDIM + kk], x1 = C[c * DDIM + kk + 1];
    float a0, a1, b0, b1;
    split2h(x0, a0, a1);
    split2h(x1, b0, b1);
    g_bfrag[idx] = pack_h2((s == 0) ? a0 : a1, (s == 0) ? b0 : b1);
}

// ---------------- persistent fused fp16x2 HMMA + argmin + scatter ----------
// 152 CTAs (1/SM), work-stealing over 128-point tiles via g_tilectr.
// smem: A fragments [split(2)][blk(64)=mtile*8+ks][lane(32)] x uint4 = 64 KB.
__global__ void __launch_bounds__(256, 1)
assign_kernel(const float* __restrict__ F, int N, int ntiles,
              float* __restrict__ out_assign) {
    extern __shared__ char smem[];
    uint32_t* As   = (uint32_t*)smem;              // 65536 B
    float*    c2s  = (float*)(smem + 65536);       // 2 KB
    float*    redv = (float*)(smem + 67584);       // 2 KB
    int*      redj = (int*)(smem + 69632);         // 2 KB
    __shared__ int s_tile;

    const int tid = threadIdx.x;
    const int lane = tid & 31, wid = tid >> 5;
    const int wm = wid >> 2, wn = wid & 3;
    const int g = lane >> 2, tg = lane & 3;

    c2s[tid]       = g_c2[tid];
    c2s[tid + 256] = g_c2[tid + 256];

    const int NCMB[2] = {2, 1};   // combos per A-split: h0*(g0,g1), h1*g0

    for (;;) {
        if (tid == 0) s_tile = atomicAdd(&g_tilectr, 1);
        __syncthreads();
        const int tile = s_tile;
        if (tile >= ntiles) break;
        const long base = (long)tile * 128;

        // ---- convert A (F tile) into fragment-ordered smem, 2 splits ----
        #pragma unroll
        for (int i = 0; i < 8; ++i) {
            int blk = (tid >> 5) + i * 8;          // 0..63: mtile*8 + ks
            int mt = blk >> 3, ks = blk & 7;
            long rA = base + mt * 16 + g;
            long rB = rA + 8;
            if (rA > (long)N - 1) rA = (long)N - 1;
            if (rB > (long)N - 1) rB = (long)N - 1;
            int kc = ks * 16 + 2 * tg;
            const float* F0 = F + (size_t)rA * DDIM;
            const float* F1 = F + (size_t)rB * DDIM;
            float2 p00 = *(const float2*)(F0 + kc);
            float2 p10 = *(const float2*)(F1 + kc);
            float2 p01 = *(const float2*)(F0 + kc + 8);
            float2 p11 = *(const float2*)(F1 + kc + 8);

            float x0[2], y0[2], x1[2], y1[2], x2[2], y2[2], x3[2], y3[2];
            split2h(p00.x, x0[0], x0[1]); split2h(p00.y, y0[0], y0[1]);
            split2h(p10.x, x1[0], x1[1]); split2h(p10.y, y1[0], y1[1]);
            split2h(p01.x, x2[0], x2[1]); split2h(p01.y, y2[0], y2[1]);
            split2h(p11.x, x3[0], x3[1]); split2h(p11.y, y3[0], y3[1]);

            #pragma unroll
            for (int s = 0; s < 2; ++s) {
                uint4 v;
                v.x = pack_h2(x0[s], y0[s]);
                v.y = pack_h2(x1[s], y1[s]);
                v.z = pack_h2(x2[s], y2[s]);
                v.w = pack_h2(x3[s], y3[s]);
                *(uint4*)(As + ((size_t)(s * 64 + blk) * 32 + lane) * 4) = v;
            }
        }
        __syncthreads();

        float bestv[4][2];
        int   bestj[4][2];
        #pragma unroll
        for (int mt = 0; mt < 4; ++mt)
            #pragma unroll
            for (int d = 0; d < 2; ++d) {
                bestv[mt][d] = 3.402823466e38f; bestj[mt][d] = 0x7fffffff;
            }

        for (int ct = 0; ct < 4; ++ct) {
            float acc[4][4][4];
            #pragma unroll
            for (int mt = 0; mt < 4; ++mt)
                #pragma unroll
                for (int nt = 0; nt < 4; ++nt)
                    #pragma unroll
                    for (int q = 0; q < 4; ++q) acc[mt][nt][q] = 0.0f;

            const uint32_t* Bb[2];
            #pragma unroll
            for (int s = 0; s < 2; ++s)
                Bb[s] = g_bfrag + (size_t)(s * 4 + ct) * 8 * 16 * 32 * 2
                      + ((size_t)(wn * 4) * 32 + lane) * 2;

            uint2 bf[2][4];
            #pragma unroll
            for (int s = 0; s < 2; ++s)
                #pragma unroll
                for (int nt = 0; nt < 4; ++nt)
                    bf[s][nt] = *(const uint2*)(Bb[s] + (size_t)nt * 32 * 2);

            #pragma unroll
            for (int ks = 0; ks < 8; ++ks) {
                uint2 bfn[2][4];
                if (ks < 7) {
                    #pragma unroll
                    for (int s = 0; s < 2; ++s)
                        #pragma unroll
                        for (int nt = 0; nt < 4; ++nt)
                            bfn[s][nt] = *(const uint2*)(Bb[s] +
                                ((size_t)(ks + 1) * 16 + nt) * 32 * 2);
                }

                uint4 af[2][4];
                #pragma unroll
                for (int sa = 0; sa < 2; ++sa)
                    #pragma unroll
                    for (int mt = 0; mt < 4; ++mt)
                        af[sa][mt] = *(const uint4*)(As +
                            ((size_t)(sa * 64 + (wm * 4 + mt) * 8 + ks) * 32 + lane) * 4);

                #pragma unroll
                for (int sa = 0; sa < 2; ++sa)
                    #pragma unroll
                    for (int sb = 0; sb < 2; ++sb) {
                        if (sb >= NCMB[sa]) break;
                        #pragma unroll
                        for (int mt = 0; mt < 4; ++mt)
                            #pragma unroll
                            for (int nt = 0; nt < 4; ++nt)
                                mma16816(acc[mt][nt], (const uint32_t*)&af[sa][mt],
                                         &bf[sb][nt].x);
                    }

                #pragma unroll
                for (int s = 0; s < 2; ++s)
                    #pragma unroll
                    for (int nt = 0; nt < 4; ++nt)
                        bf[s][nt] = bfn[s][nt];
            }

            // epilogue: score = c2 - 2*dot, fold into running argmin
            #pragma unroll
            for (int mt = 0; mt < 4; ++mt)
                #pragma unroll
                for (int nt = 0; nt < 4; ++nt) {
                    int col = ct * 128 + wn * 32 + nt * 8 + 2 * tg;
                    float c2a = c2s[col], c2b = c2s[col + 1];
                    upd(bestv[mt][0], bestj[mt][0], fmaf(-2.0f, acc[mt][nt][0], c2a), col);
                    upd(bestv[mt][0], bestj[mt][0], fmaf(-2.0f, acc[mt][nt][1], c2b), col + 1);
                    upd(bestv[mt][1], bestj[mt][1], fmaf(-2.0f, acc[mt][nt][2], c2a), col);
                    upd(bestv[mt][1], bestj[mt][1], fmaf(-2.0f, acc[mt][nt][3], c2b), col + 1);
                }
        }

        // ---- reduce: across tg (4 lanes) then across wn (4 warps) ----
        #pragma unroll
        for (int mt = 0; mt < 4; ++mt)
            #pragma unroll
            for (int d = 0; d < 2; ++d) {
                float v = bestv[mt][d];
                int   j = bestj[mt][d];
                #pragma unroll
                for (int off = 1; off <= 2; off <<= 1) {
                    float vo = __shfl_xor_sync(0xffffffffu, v, off);
                    int   jo = __shfl_xor_sync(0xffffffffu, j, off);
                    if (vo < v || (vo == v && jo < j)) { v = vo; j = jo; }
                }
                if (tg == 0) {
                    int row = wm * 64 + mt * 16 + g + d * 8;
                    redv[row * 4 + wn] = v;
                    redj[row * 4 + wn] = j;
                }
            }
        __syncthreads();

        if (tid < 128) {
            float v = redv[tid * 4];
            int   j = redj[tid * 4];
            #pragma unroll
            for (int w = 1; w < 4; ++w) {
                float v2 = redv[tid * 4 + w];
                int   j2 = redj[tid * 4 + w];
                if (v2 < v || (v2 == v && j2 < j)) { v = v2; j = j2; }
            }
            long p = base + tid;
            if (p < N) {
                out_assign[p] = (float)j;
                atomicAdd(&g_counts[j], 1);
            }
            redj[tid] = j;          // publish for scatter phase
        }
        __syncthreads();

        // ---- fused scatter: red.v4 of F rows into g_sums ----
        const int npts = (int)((base + 128 <= (long)N) ? 128 : (N - base));
        for (int i = tid; i < npts * 32; i += 256) {
            int pt = i >> 5;
            int ch = i & 31;
            float4 v = ((const float4*)(F + (size_t)(base + pt) * DDIM))[ch];
            red_add_v4(g_sums + (size_t)redj[pt] * DDIM + ch * 4, v);
        }
        // next iteration's post-A-convert barrier orders s_tile reuse
    }
}

// ---------------- finalize -------------------------------------------------
__global__ void finalize_kernel(float* __restrict__ out_centers) {
    int i = blockIdx.x * blockDim.x + threadIdx.x;
    if (i < KC * DDIM) {
        int k = i >> 7;
        float cnt = fmaxf((float)g_counts[k], 1.0f);
        out_centers[i] = g_sums[i] / cnt;
    }
}

// ---------------- launch ---------------------------------------------------
extern "C" void kernel_launch(void* const* d_in, const int* in_sizes, int n_in,
                              void* d_out, int out_size) {
    const float* F = (const float*)d_in[0];
    const float* C = (const float*)d_in[1];
    const int N = in_sizes[0] / DDIM;
    const int ntiles = (N + 127) / 128;

    float* out = (float*)d_out;
    float* out_centers = out;
    float* out_assign  = out + KC * DDIM;

    prep_kernel<<<KC, DDIM>>>(C);

    const int smem_bytes = 65536 + 2048 + 2048 + 2048;   // 71680
    cudaFuncSetAttribute(assign_kernel,
                         cudaFuncAttributeMaxDynamicSharedMemorySize, smem_bytes);
    assign_kernel<<<152, 256, smem_bytes>>>(F, N, ntiles, out_assign);

    finalize_kernel<<<(KC * DDIM + 255) / 256, 256>>>(out_centers);
}

// round 12
// speedup vs baseline: 4.3188x; 1.1822x over previous
#include <cuda_runtime.h>
#include <cuda_fp16.h>
#include <cstdint>
#include <cstddef>

#define KC   512
#define DDIM 128

// ---------------- device scratch (no allocation allowed) -------------------
__device__ float    g_c2[KC];
__device__ float    g_sums[KC * DDIM];
__device__ int      g_counts[KC];
__device__ int      g_tilectr;
// B fragments: [split(2)][ctile(4)][kstep(8)][ntile(16)][lane(32)][reg(2)]
__device__ uint32_t g_bfrag[2 * 4 * 8 * 16 * 32 * 2];   // 65536 u32 = 256 KB

// ---------------- helpers ---------------------------------------------------
__device__ __forceinline__ void split2h(float x, float& s0, float& s1) {
    s0 = __half2float(__float2half_rn(x));
    s1 = x - s0;                       // exact in fp32; fp16(s1) carries 11 more bits
}
__device__ __forceinline__ uint32_t pack_h2(float lo, float hi) {
    __half l = __float2half_rn(lo), h = __float2half_rn(hi);
    uint16_t lb, hb;
    memcpy(&lb, &l, 2); memcpy(&hb, &h, 2);
    return (uint32_t)lb | ((uint32_t)hb << 16);
}
__device__ __forceinline__ void mma16816(float* d, const uint32_t* a, const uint32_t* b) {
    asm volatile(
        "mma.sync.aligned.m16n8k16.row.col.f32.f16.f16.f32 "
        "{%0,%1,%2,%3}, {%4,%5,%6,%7}, {%8,%9}, {%0,%1,%2,%3};"
        : "+f"(d[0]), "+f"(d[1]), "+f"(d[2]), "+f"(d[3])
        : "r"(a[0]), "r"(a[1]), "r"(a[2]), "r"(a[3]), "r"(b[0]), "r"(b[1]));
}
__device__ __forceinline__ void upd(float& bv, int& bj, float v, int j) {
    if (v < bv || (v == bv && j < bj)) { bv = v; bj = j; }
}
__device__ __forceinline__ void red_add_v4(float* gptr, float4 v) {
    asm volatile("red.global.add.v4.f32 [%0], {%1,%2,%3,%4};"
                 :: "l"(gptr), "f"(v.x), "f"(v.y), "f"(v.z), "f"(v.w)
                 : "memory");
}

// ---------------- prep (fused): zero sums/counts/ctr, ||c||^2, B frags -----
__global__ void prep_kernel(const float* __restrict__ C) {
    int k = blockIdx.x, t = threadIdx.x;
    g_sums[k * DDIM + t] = 0.0f;
    if (t == 0) g_counts[k] = 0;
    if (k == 0 && t == 0) g_tilectr = 0;

    float v = C[k * DDIM + t];
    v *= v;
    #pragma unroll
    for (int off = 16; off >= 1; off >>= 1) v += __shfl_down_sync(0xffffffffu, v, off);
    __shared__ float red[4];
    if ((t & 31) == 0) red[t >> 5] = v;
    __syncthreads();
    if (t == 0) g_c2[k] = (red[0] + red[1]) + (red[2] + red[3]);

    int idx = k * 128 + t;                         // < 65536
    int r    = idx & 1;
    int lane = (idx >> 1) & 31;
    int nt   = (idx >> 6) & 15;
    int ks   = (idx >> 10) & 7;
    int ct   = (idx >> 13) & 3;
    int s    = idx >> 15;                          // 0..1
    int g = lane >> 2, tg = lane & 3;
    int c = ct * 128 + nt * 8 + g;
    int kk = ks * 16 + 2 * tg + r * 8;
    float x0 = C[c * DDIM + kk], x1 = C[c * DDIM + kk + 1];
    float a0, a1, b0, b1;
    split2h(x0, a0, a1);
    split2h(x1, b0, b1);
    g_bfrag[idx] = pack_h2((s == 0) ? a0 : a1, (s == 0) ? b0 : b1);
}

// ---------------- persistent fused fp16x2 HMMA + argmin + scatter ----------
// 64-point tiles, 2 CTAs/SM (one CTA's MMA hides the other's serial phases).
// 8 warps, warp tile 32x32 (wm in 0..1, wn in 0..3).
// smem: A frags [split(2)][blk(32)=mt*8+ks][lane(32)] x uint4 = 32 KB.
#define SM_C2    32768
#define SM_REDV  34816
#define SM_REDJ  35840
#define SM_JFIN  36864
#define SM_TOTAL 37184

__global__ void __launch_bounds__(256, 2)
assign_kernel(const float* __restrict__ F, int N, int ntiles,
              float* __restrict__ out_assign) {
    extern __shared__ char smem[];
    uint32_t* As   = (uint32_t*)smem;                  // 32768 B
    float*    c2s  = (float*)(smem + SM_C2);           // 2 KB
    float*    redv = (float*)(smem + SM_REDV);         // 64*4 floats
    int*      redj = (int*)(smem + SM_REDJ);           // 64*4 ints
    int*      jfin = (int*)(smem + SM_JFIN);           // 64 ints
    __shared__ int s_tile;

    const int tid = threadIdx.x;
    const int lane = tid & 31, wid = tid >> 5;
    const int wm = wid >> 2, wn = wid & 3;
    const int g = lane >> 2, tg = lane & 3;

    c2s[tid]       = g_c2[tid];
    c2s[tid + 256] = g_c2[tid + 256];

    const int NCMB[2] = {2, 1};   // combos per A-split: h0*(g0,g1), h1*g0

    for (;;) {
        if (tid == 0) s_tile = atomicAdd(&g_tilectr, 1);
        __syncthreads();
        const int tile = s_tile;
        if (tile >= ntiles) break;
        const long base = (long)tile * 64;

        // ---- convert A (F tile, 64 rows) into fragment smem, 2 splits ----
        #pragma unroll
        for (int i = 0; i < 4; ++i) {
            int blk = wid + i * 8;                 // 0..31: mt*8 + ks
            int mt = blk >> 3, ks = blk & 7;
            long rA = base + mt * 16 + g;
            long rB = rA + 8;
            if (rA > (long)N - 1) rA = (long)N - 1;
            if (rB > (long)N - 1) rB = (long)N - 1;
            int kc = ks * 16 + 2 * tg;
            const float* F0 = F + (size_t)rA * DDIM;
            const float* F1 = F + (size_t)rB * DDIM;
            float2 p00 = *(const float2*)(F0 + kc);
            float2 p10 = *(const float2*)(F1 + kc);
            float2 p01 = *(const float2*)(F0 + kc + 8);
            float2 p11 = *(const float2*)(F1 + kc + 8);

            float x0[2], y0[2], x1[2], y1[2], x2[2], y2[2], x3[2], y3[2];
            split2h(p00.x, x0[0], x0[1]); split2h(p00.y, y0[0], y0[1]);
            split2h(p10.x, x1[0], x1[1]); split2h(p10.y, y1[0], y1[1]);
            split2h(p01.x, x2[0], x2[1]); split2h(p01.y, y2[0], y2[1]);
            split2h(p11.x, x3[0], x3[1]); split2h(p11.y, y3[0], y3[1]);

            #pragma unroll
            for (int s = 0; s < 2; ++s) {
                uint4 v;
                v.x = pack_h2(x0[s], y0[s]);
                v.y = pack_h2(x1[s], y1[s]);
                v.z = pack_h2(x2[s], y2[s]);
                v.w = pack_h2(x3[s], y3[s]);
                *(uint4*)(As + ((size_t)(s * 32 + blk) * 32 + lane) * 4) = v;
            }
        }
        __syncthreads();

        float bestv[2][2];
        int   bestj[2][2];
        #pragma unroll
        for (int mt = 0; mt < 2; ++mt)
            #pragma unroll
            for (int d = 0; d < 2; ++d) {
                bestv[mt][d] = 3.402823466e38f; bestj[mt][d] = 0x7fffffff;
            }

        for (int ct = 0; ct < 4; ++ct) {
            float acc[2][4][4];
            #pragma unroll
            for (int mt = 0; mt < 2; ++mt)
                #pragma unroll
                for (int nt = 0; nt < 4; ++nt)
                    #pragma unroll
                    for (int q = 0; q < 4; ++q) acc[mt][nt][q] = 0.0f;

            const uint32_t* Bb[2];
            #pragma unroll
            for (int s = 0; s < 2; ++s)
                Bb[s] = g_bfrag + (size_t)(s * 4 + ct) * 8 * 16 * 32 * 2
                      + ((size_t)(wn * 4) * 32 + lane) * 2;

            uint2 bf[2][4];
            #pragma unroll
            for (int s = 0; s < 2; ++s)
                #pragma unroll
                for (int nt = 0; nt < 4; ++nt)
                    bf[s][nt] = *(const uint2*)(Bb[s] + (size_t)nt * 32 * 2);

            #pragma unroll
            for (int ks = 0; ks < 8; ++ks) {
                uint2 bfn[2][4];
                if (ks < 7) {
                    #pragma unroll
                    for (int s = 0; s < 2; ++s)
                        #pragma unroll
                        for (int nt = 0; nt < 4; ++nt)
                            bfn[s][nt] = *(const uint2*)(Bb[s] +
                                ((size_t)(ks + 1) * 16 + nt) * 32 * 2);
                }

                uint4 af[2][2];
                #pragma unroll
                for (int sa = 0; sa < 2; ++sa)
                    #pragma unroll
                    for (int mt = 0; mt < 2; ++mt)
                        af[sa][mt] = *(const uint4*)(As +
                            ((size_t)(sa * 32 + (wm * 2 + mt) * 8 + ks) * 32 + lane) * 4);

                #pragma unroll
                for (int sa = 0; sa < 2; ++sa)
                    #pragma unroll
                    for (int sb = 0; sb < 2; ++sb) {
                        if (sb >= NCMB[sa]) break;
                        #pragma unroll
                        for (int mt = 0; mt < 2; ++mt)
                            #pragma unroll
                            for (int nt = 0; nt < 4; ++nt)
                                mma16816(acc[mt][nt], (const uint32_t*)&af[sa][mt],
                                         &bf[sb][nt].x);
                    }

                #pragma unroll
                for (int s = 0; s < 2; ++s)
                    #pragma unroll
                    for (int nt = 0; nt < 4; ++nt)
                        bf[s][nt] = bfn[s][nt];
            }

            // epilogue: score = c2 - 2*dot, fold into running argmin
            #pragma unroll
            for (int mt = 0; mt < 2; ++mt)
                #pragma unroll
                for (int nt = 0; nt < 4; ++nt) {
                    int col = ct * 128 + wn * 32 + nt * 8 + 2 * tg;
                    float c2a = c2s[col], c2b = c2s[col + 1];
                    upd(bestv[mt][0], bestj[mt][0], fmaf(-2.0f, acc[mt][nt][0], c2a), col);
                    upd(bestv[mt][0], bestj[mt][0], fmaf(-2.0f, acc[mt][nt][1], c2b), col + 1);
                    upd(bestv[mt][1], bestj[mt][1], fmaf(-2.0f, acc[mt][nt][2], c2a), col);
                    upd(bestv[mt][1], bestj[mt][1], fmaf(-2.0f, acc[mt][nt][3], c2b), col + 1);
                }
        }

        // ---- reduce: across tg (4 lanes) then across wn (4 warps) ----
        #pragma unroll
        for (int mt = 0; mt < 2; ++mt)
            #pragma unroll
            for (int d = 0; d < 2; ++d) {
                float v = bestv[mt][d];
                int   j = bestj[mt][d];
                #pragma unroll
                for (int off = 1; off <= 2; off <<= 1) {
                    float vo = __shfl_xor_sync(0xffffffffu, v, off);
                    int   jo = __shfl_xor_sync(0xffffffffu, j, off);
                    if (vo < v || (vo == v && jo < j)) { v = vo; j = jo; }
                }
                if (tg == 0) {
                    int row = wm * 32 + mt * 16 + g + d * 8;   // 0..63
                    redv[row * 4 + wn] = v;
                    redj[row * 4 + wn] = j;
                }
            }
        __syncthreads();

        if (tid < 64) {
            float v = redv[tid * 4];
            int   j = redj[tid * 4];
            #pragma unroll
            for (int w = 1; w < 4; ++w) {
                float v2 = redv[tid * 4 + w];
                int   j2 = redj[tid * 4 + w];
                if (v2 < v || (v2 == v && j2 < j)) { v = v2; j = j2; }
            }
            long p = base + tid;
            if (p < N) {
                out_assign[p] = (float)j;
                atomicAdd(&g_counts[j], 1);
            }
            jfin[tid] = j;          // dedicated array: no alias with redj reads
        }
        __syncthreads();

        // ---- fused scatter: red.v4 of F rows into g_sums ----
        const int npts = (int)((base + 64 <= (long)N) ? 64 : (N - base));
        for (int i = tid; i < npts * 32; i += 256) {
            int pt = i >> 5;
            int ch = i & 31;
            float4 v = ((const float4*)(F + (size_t)(base + pt) * DDIM))[ch];
            red_add_v4(g_sums + (size_t)jfin[pt] * DDIM + ch * 4, v);
        }
        // next iteration's post-A-convert barrier orders s_tile/jfin reuse
    }
}

// ---------------- finalize -------------------------------------------------
__global__ void finalize_kernel(float* __restrict__ out_centers) {
    int i = blockIdx.x * blockDim.x + threadIdx.x;
    if (i < KC * DDIM) {
        int k = i >> 7;
        float cnt = fmaxf((float)g_counts[k], 1.0f);
        out_centers[i] = g_sums[i] / cnt;
    }
}

// ---------------- launch ---------------------------------------------------
extern "C" void kernel_launch(void* const* d_in, const int* in_sizes, int n_in,
                              void* d_out, int out_size) {
    const float* F = (const float*)d_in[0];
    const float* C = (const float*)d_in[1];
    const int N = in_sizes[0] / DDIM;
    const int ntiles = (N + 63) / 64;

    float* out = (float*)d_out;
    float* out_centers = out;
    float* out_assign  = out + KC * DDIM;

    prep_kernel<<<KC, DDIM>>>(C);

    cudaFuncSetAttribute(assign_kernel,
                         cudaFuncAttributeMaxDynamicSharedMemorySize, SM_TOTAL);
    assign_kernel<<<304, 256, SM_TOTAL>>>(F, N, ntiles, out_assign);

    finalize_kernel<<<(KC * DDIM + 255) / 256, 256>>>(out_centers);
}